// round 5
// baseline (speedup 1.0000x reference)
#include <cuda_runtime.h>
#include <cuda_bf16.h>
#include <limits.h>

// StreamingRhythmProjector on GB300 — v4: traffic-reduced version.
//
// Key ideas vs v3 (51.7us kernel, DRAM-traffic-bound):
//  * unit_mask is a prefix mask -> recover `visible` by warp-parallel binary
//    search (~2KB probes/row) instead of streaming 8KB/row.
//  * open_run_mask: only the first OPEN_N elements are loaded eagerly
//    (first_open is tiny w.h.p.); guarded fallback scan for the tail.
//  * Bulk loads are issued before the search so the probe latency overlaps.
//
// Output (f32 flat): speech[B*U] | pause[B*U] | effective[B*U] |
//                    commit[B] | next_phase[B] | next_backlog[B] | next_clock[B]

#define BS 512
#define NW (BS / 32)
#define OPEN_N 512   // open_run prefix loaded eagerly (elements)

__device__ __forceinline__ float warpSum(float v) {
    #pragma unroll
    for (int o = 16; o > 0; o >>= 1) v += __shfl_down_sync(0xffffffffu, v, o);
    return v;
}
__device__ __forceinline__ int warpMin(int v) {
    #pragma unroll
    for (int o = 16; o > 0; o >>= 1) v = min(v, __shfl_down_sync(0xffffffffu, v, o));
    return v;
}

// ---------------------------------------------------------------------------
// Fast kernel: U % 4 == 0 and U <= BS*4, prefix unit_mask.
// ---------------------------------------------------------------------------
__global__ __launch_bounds__(BS, 3)
void rhythm_projector_v4(
    const float* __restrict__ anchor_src,
    const float* __restrict__ unit_mask,
    const float* __restrict__ speech_budget,
    const float* __restrict__ pause_budget,
    const float* __restrict__ lr_unit,
    const float* __restrict__ pw_unit,
    const float* __restrict__ bl_unit,
    const float* __restrict__ phase_ptr,
    const float* __restrict__ backlog,
    const float* __restrict__ clock_delta,
    const int*   __restrict__ commit_frontier,
    const int*   __restrict__ open_run,
    float* __restrict__ out,
    int B, int U)
{
    const int row = blockIdx.x;
    const int tid = threadIdx.x;
    const size_t base = (size_t)row * (size_t)U;
    const size_t BU = (size_t)B * (size_t)U;

    __shared__ float4 s_sp[BS];
    __shared__ float4 s_sc[BS];
    __shared__ float s_f0[NW], s_f1[NW], s_f2[NW];
    __shared__ int   s_i0[NW];
    __shared__ float s_bcast[3];
    __shared__ int   s_visible, s_first;

    const int j = tid * 4;
    const bool in = (j < U);

    // -------- issue bulk loads first (latency overlapped with search) -------
    float4 ar = make_float4(0.f, 0.f, 0.f, 0.f);
    float4 lr = ar, pw = ar, bl = ar;
    int4   op = make_int4(0, 0, 0, 0);
    if (in) {
        ar = __ldcs((const float4*)(anchor_src + base + j));
        lr = __ldcs((const float4*)(lr_unit    + base + j));
        pw = __ldcs((const float4*)(pw_unit    + base + j));
        bl = __ldcs((const float4*)(bl_unit    + base + j));
        if (j < OPEN_N) op = __ldcs((const int4*)(open_run + base + j));
    }

    // -------- warp 0: binary search for prefix length (visible) -------------
    if (tid < 32) {
        int lo = 0, hi = U;   // invariant: L in [lo, hi], mask monotone 1..1 0..0
        while (hi > lo) {
            const int step = (hi - lo + 31) >> 5;
            const int p = lo + tid * step;
            bool one = false;
            if (p < hi) one = (__ldg(unit_mask + base + p) > 0.5f);
            const unsigned ball = __ballot_sync(0xffffffffu, one);
            const int n1 = __popc(ball);
            if (n1 == 0) {
                hi = lo;                       // mask[lo]==0 -> L==lo
            } else {
                const int nl = lo + (n1 - 1) * step + 1;
                const int f0 = lo + n1 * step; // first 0-probe (if real)
                hi = (f0 < hi) ? f0 : hi;
                lo = nl;
            }
        }
        if (tid == 0) s_visible = lo;
    }
    __syncthreads();
    const int visible = s_visible;

    // -------- elementwise -> smem staging + partial sums --------------------
    float sum_sp = 0.f, sum_sc = 0.f;
    int first_open = INT_MAX;
    {
        float4 spv = make_float4(0.f, 0.f, 0.f, 0.f);
        float4 scv = spv;
        if (in) {
            #define ELEM(c, e)                                                    \
            {                                                                     \
                const int je = j + e;                                             \
                if (je < visible) {                                               \
                    const float a = fmaxf(ar.c, 1.0f);                            \
                    const float bb = a * __expf(lr.c);                            \
                    spv.c = fmaxf(fminf(bb, a * 3.0f), 1.0f);                     \
                    scv.c = fmaxf(pw.c, 0.f) * (0.5f + bl.c);                     \
                    if (op.c > 0) first_open = min(first_open, je);               \
                }                                                                 \
            }
            ELEM(x, 0) ELEM(y, 1) ELEM(z, 2) ELEM(w, 3)
            #undef ELEM
            sum_sp = (spv.x + spv.y) + (spv.z + spv.w);
            sum_sc = (scv.x + scv.y) + (scv.z + scv.w);
        }
        s_sp[tid] = spv;
        s_sc[tid] = scv;
    }

    // -------- block reduction (sum_sp, sum_sc, min first_open) --------------
    {
        float w0 = warpSum(sum_sp);
        float w1 = warpSum(sum_sc);
        int   w3 = warpMin(first_open);
        const int wid = tid >> 5, lid = tid & 31;
        if (lid == 0) { s_f0[wid] = w0; s_f1[wid] = w1; s_i0[wid] = w3; }
        __syncthreads();
        if (wid == 0) {
            float v0 = (lid < NW) ? s_f0[lid] : 0.f;
            float v1 = (lid < NW) ? s_f1[lid] : 0.f;
            int   v3 = (lid < NW) ? s_i0[lid] : INT_MAX;
            #pragma unroll
            for (int o = 8; o > 0; o >>= 1) {
                v0 += __shfl_down_sync(0xffffffffu, v0, o);
                v1 += __shfl_down_sync(0xffffffffu, v1, o);
                v3 = min(v3, __shfl_down_sync(0xffffffffu, v3, o));
            }
            if (lid == 0) { s_bcast[0] = v0; s_bcast[1] = v1; s_first = v3; }
        }
        __syncthreads();
        sum_sp = s_bcast[0]; sum_sc = s_bcast[1];
        first_open = s_first;
    }

    // -------- rare fallback: no open found in prefix, visible beyond it -----
    if (first_open == INT_MAX && visible > OPEN_N && OPEN_N < U) {
        int fo = INT_MAX;
        for (int p = OPEN_N + tid; p < visible; p += BS)
            if (__ldg(open_run + base + p) > 0) { fo = min(fo, p); }
        int w3 = warpMin(fo);
        const int wid = tid >> 5, lid = tid & 31;
        if (lid == 0) s_i0[wid] = w3;
        __syncthreads();
        if (tid == 0) {
            int v3 = INT_MAX;
            #pragma unroll
            for (int i = 0; i < NW; i++) v3 = min(v3, s_i0[i]);
            s_first = v3;
        }
        __syncthreads();
        first_open = s_first;
    }

    // -------- scalar frontier logic (uniform across block) ------------------
    const float sbud = speech_budget[row];
    const float pbud = pause_budget[row];
    const float speech_scale = sbud / fmaxf(sum_sp, 1e-6f);

    const bool has_open = (first_open != INT_MAX);
    const int  closed   = has_open ? first_open : visible;
    const int  cap      = max(visible - 2, 0);   // TAIL_HOLD_UNITS
    int cand = min(cap, closed);
    const int prev = commit_frontier[row];
    const int bidx = min(max(cand - 1, 0), U - 1);
    const float bval = __ldg(bl_unit + base + bidx);   // uniform broadcast
    const bool soft = (cand > 0) && (cand < visible) && (bval < 0.45f);
    if (soft) cand = max(prev, cand - 1);
    const int commit = max(prev, cand);

    const bool  use_scores = (sum_sc > 0.f);
    const float wdenom = pbud / fmaxf(sum_sc, 1e-6f);
    const float fb     = pbud / fmaxf((float)visible, 1.f);

    // -------- Pass B: compute + streaming stores + window sums --------------
    float sum_eff = 0.f, exec_s = 0.f, src_s = 0.f;
    if (in) {
        const float4 spv = s_sp[tid];
        const float4 scv = s_sc[tid];
        float4 speech, pause, eff;

        // speech/pause are mask-proportional (prefix mask), eff = speech+pause.
        #define ELEM(c, e)                                                     \
        {                                                                      \
            speech.c = spv.c * speech_scale;                                   \
            pause.c = use_scores ? (scv.c * wdenom)                            \
                                 : (((j + e) < visible) ? fb : 0.f);           \
            eff.c = speech.c + pause.c;                                        \
            sum_eff += eff.c;                                                  \
            const int je = j + e;                                              \
            if (je >= prev && je < commit) {                                   \
                exec_s += eff.c;                                               \
                src_s  += ar.c;                                                \
            }                                                                  \
        }
        ELEM(x, 0) ELEM(y, 1) ELEM(z, 2) ELEM(w, 3)
        #undef ELEM

        __stcs((float4*)(out + base + j),          speech);
        __stcs((float4*)(out + BU + base + j),     pause);
        __stcs((float4*)(out + 2 * BU + base + j), eff);
    }

    // -------- final 3-way reduction + tail outputs --------------------------
    {
        float w0 = warpSum(sum_eff);
        float w1 = warpSum(exec_s);
        float w2 = warpSum(src_s);
        const int wid = tid >> 5, lid = tid & 31;
        __syncthreads();   // protect smem reuse
        if (lid == 0) { s_f0[wid] = w0; s_f1[wid] = w1; s_f2[wid] = w2; }
        __syncthreads();
        if (tid == 0) {
            float v0 = 0.f, v1 = 0.f, v2 = 0.f;
            #pragma unroll
            for (int i = 0; i < NW; i++) { v0 += s_f0[i]; v1 += s_f1[i]; v2 += s_f2[i]; }

            const bool adv = commit > prev;
            const float cd = clock_delta[row];
            const float next_clock = adv ? (cd + (v1 - v2)) : cd;
            const float next_backlog = adv ? fmaxf(next_clock, 0.f) : backlog[row];
            const float vt = fmaxf(v0, 1.f);
            float next_phase = phase_ptr[row];
            if (adv) next_phase = fminf(fmaxf(next_phase + v1 / vt, 0.f), 1.f);

            float* tail = out + 3 * BU;
            tail[row]         = (float)commit;
            tail[B + row]     = next_phase;
            tail[2 * B + row] = next_backlog;
            tail[3 * B + row] = next_clock;
        }
    }
}

// ---------------------------------------------------------------------------
// Scalar fallback kernel (any U, full reads, no prefix assumption)
// ---------------------------------------------------------------------------
template<int ITEMS>
__global__ __launch_bounds__(BS)
void rhythm_projector_scalar(
    const float* __restrict__ anchor_src,
    const float* __restrict__ unit_mask,
    const float* __restrict__ speech_budget,
    const float* __restrict__ pause_budget,
    const float* __restrict__ lr_unit,
    const float* __restrict__ pw_unit,
    const float* __restrict__ bl_unit,
    const float* __restrict__ phase_ptr,
    const float* __restrict__ backlog,
    const float* __restrict__ clock_delta,
    const int*   __restrict__ commit_frontier,
    const int*   __restrict__ open_run,
    float* __restrict__ out,
    int B, int U)
{
    const int row = blockIdx.x;
    const int tid = threadIdx.x;
    const size_t base = (size_t)row * (size_t)U;
    const size_t BU = (size_t)B * (size_t)U;

    __shared__ float s_f0[NW], s_f1[NW], s_f2[NW];
    __shared__ int   s_i0[NW];
    __shared__ float s_bcast[3];
    __shared__ int   s_ibcast;

    float sp[ITEMS], sc[ITEMS], msk[ITEMS];
    float sum_sp = 0.f, sum_sc = 0.f, sum_m = 0.f;
    int first_open = INT_MAX;

    #pragma unroll
    for (int k = 0; k < ITEMS; k++) {
        const int j = k * BS + tid;
        float m = 0.f, spv = 0.f, scv = 0.f;
        if (j < U) {
            const float arv = anchor_src[base + j];
            m               = unit_mask[base + j];
            const float lrv = lr_unit[base + j];
            const float pwv = pw_unit[base + j];
            const float blv = bl_unit[base + j];
            const int   opv = open_run[base + j];
            const float a   = fmaxf(arv, 1.0f);
            const float b   = a * __expf(lrv);
            spv = fmaxf(fminf(b, a * 3.0f), 1.0f) * m;
            scv = fmaxf(pwv, 0.f) * (0.5f + blv) * m;
            if (opv > 0 && m > 0.f) first_open = min(first_open, j);
        }
        sp[k] = spv; sc[k] = scv; msk[k] = m;
        sum_sp += spv; sum_sc += scv; sum_m += m;
    }

    {
        float w0 = warpSum(sum_sp), w1 = warpSum(sum_sc), w2 = warpSum(sum_m);
        int w3 = warpMin(first_open);
        const int wid = tid >> 5, lid = tid & 31;
        if (lid == 0) { s_f0[wid] = w0; s_f1[wid] = w1; s_f2[wid] = w2; s_i0[wid] = w3; }
        __syncthreads();
        if (wid == 0) {
            float v0 = (lid < NW) ? s_f0[lid] : 0.f;
            float v1 = (lid < NW) ? s_f1[lid] : 0.f;
            float v2 = (lid < NW) ? s_f2[lid] : 0.f;
            int   v3 = (lid < NW) ? s_i0[lid] : INT_MAX;
            #pragma unroll
            for (int o = 8; o > 0; o >>= 1) {
                v0 += __shfl_down_sync(0xffffffffu, v0, o);
                v1 += __shfl_down_sync(0xffffffffu, v1, o);
                v2 += __shfl_down_sync(0xffffffffu, v2, o);
                v3 = min(v3, __shfl_down_sync(0xffffffffu, v3, o));
            }
            if (lid == 0) { s_bcast[0] = v0; s_bcast[1] = v1; s_bcast[2] = v2; s_ibcast = v3; }
        }
        __syncthreads();
        sum_sp = s_bcast[0]; sum_sc = s_bcast[1]; sum_m = s_bcast[2];
        first_open = s_ibcast;
    }

    const float sbud = speech_budget[row];
    const float pbud = pause_budget[row];
    const float speech_scale = sbud / fmaxf(sum_sp, 1e-6f);
    const int  visible  = (int)sum_m;
    const bool has_open = (first_open != INT_MAX);
    const int  closed   = has_open ? first_open : visible;
    const int  cap      = max(visible - 2, 0);
    int cand = min(cap, closed);
    const int prev = commit_frontier[row];
    const int bidx = min(max(cand - 1, 0), U - 1);
    const float bval = __ldg(bl_unit + base + bidx);
    const bool soft = (cand > 0) && (cand < visible) && (bval < 0.45f);
    if (soft) cand = max(prev, cand - 1);
    const int commit = max(prev, cand);

    const bool  use_scores = (sum_sc > 0.f);
    const float wdenom = 1.f / fmaxf(sum_sc, 1e-6f);
    const float fb     = 1.f / fmaxf(sum_m, 1.f);

    float sum_eff = 0.f, exec_s = 0.f, src_s = 0.f;
    #pragma unroll
    for (int k = 0; k < ITEMS; k++) {
        const int j = k * BS + tid;
        if (j < U) {
            const float speech = sp[k] * speech_scale;
            const float w      = use_scores ? (sc[k] * wdenom) : (msk[k] * fb);
            const float pause  = w * pbud;
            const float eff    = (speech + pause) * msk[k];
            out[base + j]          = speech;
            out[BU + base + j]     = pause;
            out[2 * BU + base + j] = eff;
            sum_eff += eff;
            if (j >= prev && j < commit) {
                exec_s += eff;
                src_s  += __ldg(anchor_src + base + j);
            }
        }
    }

    {
        float w0 = warpSum(sum_eff), w1 = warpSum(exec_s), w2 = warpSum(src_s);
        const int wid = tid >> 5, lid = tid & 31;
        if (lid == 0) { s_f0[wid] = w0; s_f1[wid] = w1; s_f2[wid] = w2; }
        __syncthreads();
        if (tid == 0) {
            float v0 = 0.f, v1 = 0.f, v2 = 0.f;
            #pragma unroll
            for (int i = 0; i < NW; i++) { v0 += s_f0[i]; v1 += s_f1[i]; v2 += s_f2[i]; }
            const bool adv = commit > prev;
            const float cd = clock_delta[row];
            const float next_clock = adv ? (cd + (v1 - v2)) : cd;
            const float next_backlog = adv ? fmaxf(next_clock, 0.f) : backlog[row];
            const float vt = fmaxf(v0, 1.f);
            float next_phase = phase_ptr[row];
            if (adv) next_phase = fminf(fmaxf(next_phase + v1 / vt, 0.f), 1.f);
            float* tail = out + 3 * BU;
            tail[row]         = (float)commit;
            tail[B + row]     = next_phase;
            tail[2 * B + row] = next_backlog;
            tail[3 * B + row] = next_clock;
        }
    }
}

extern "C" void kernel_launch(void* const* d_in, const int* in_sizes, int n_in,
                              void* d_out, int out_size)
{
    const float* anchor_src  = (const float*)d_in[0];
    const float* unit_mask   = (const float*)d_in[1];
    const float* sbud        = (const float*)d_in[2];
    const float* pbud        = (const float*)d_in[3];
    const float* lr_unit     = (const float*)d_in[4];
    const float* pw_unit     = (const float*)d_in[5];
    const float* bl_unit     = (const float*)d_in[6];
    const float* phase_ptr   = (const float*)d_in[7];
    const float* backlog     = (const float*)d_in[8];
    const float* clock_delta = (const float*)d_in[9];
    const int*   frontier    = (const int*)d_in[10];
    const int*   open_run    = (const int*)d_in[11];
    float* out = (float*)d_out;

    const int B = in_sizes[2];            // speech_budget_win has B elements
    const int U = in_sizes[0] / B;        // dur_anchor_src has B*U

    dim3 grid(B), block(BS);

    if ((U & 3) == 0 && U <= BS * 4) {
        rhythm_projector_v4<<<grid, block>>>(anchor_src, unit_mask, sbud, pbud,
            lr_unit, pw_unit, bl_unit, phase_ptr, backlog, clock_delta, frontier,
            open_run, out, B, U);
    } else {
        const int items = (U + BS - 1) / BS;
        #define LAUNCH(N) rhythm_projector_scalar<N><<<grid, block>>>(anchor_src,    \
            unit_mask, sbud, pbud, lr_unit, pw_unit, bl_unit, phase_ptr, backlog,    \
            clock_delta, frontier, open_run, out, B, U)
        if      (items <= 4)  LAUNCH(4);
        else if (items <= 8)  LAUNCH(8);
        else if (items <= 16) LAUNCH(16);
        else                  LAUNCH(32);
        #undef LAUNCH
    }
}

// round 6
// speedup vs baseline: 1.1443x; 1.1443x over previous
#include <cuda_runtime.h>
#include <cuda_bf16.h>
#include <limits.h>

// StreamingRhythmProjector on GB300 — v5: two-kernel traffic-reduced pipeline.
//
// Lesson from v4: a mask binary-search inside the streaming CTA serializes
// (warp 0 does 3-4 dependent DRAM round-trips while 15 warps idle) and
// regressed despite saving bytes. v5 moves ALL irregular work into a tiny
// pre-kernel where 4096 row-searches run concurrently (latency fully
// overlapped across rows), then the streaming kernel never reads unit_mask
// or open_run at all (-64MB, -22% traffic).
//
// Output (f32 flat): speech[B*U] | pause[B*U] | effective[B*U] |
//                    commit[B] | next_phase[B] | next_backlog[B] | next_clock[B]

#define BS 512
#define NW (BS / 32)
#define MAX_ROWS 65536

__device__ static int g_visible[MAX_ROWS];
__device__ static int g_first[MAX_ROWS];

__device__ __forceinline__ float warpSum(float v) {
    #pragma unroll
    for (int o = 16; o > 0; o >>= 1) v += __shfl_down_sync(0xffffffffu, v, o);
    return v;
}
__device__ __forceinline__ int warpMin(int v) {
    #pragma unroll
    for (int o = 16; o > 0; o >>= 1) v = min(v, __shfl_down_sync(0xffffffffu, v, o));
    return v;
}

// ---------------------------------------------------------------------------
// Pre-kernel: one warp per row. Computes
//   g_visible[row] = prefix length of unit_mask (binary search, ~3 rounds)
//   g_first[row]   = first j < visible with open_run[j] > 0 (chunked scan),
//                    INT_MAX if none.
// All rows' dependent-latency chains overlap across the grid.
// ---------------------------------------------------------------------------
__global__ __launch_bounds__(256)
void precompute_row_stats(const float* __restrict__ unit_mask,
                          const int*   __restrict__ open_run,
                          int B, int U)
{
    const int warp = blockIdx.x * (blockDim.x >> 5) + (threadIdx.x >> 5);
    const int lane = threadIdx.x & 31;
    if (warp >= B) return;
    const size_t base = (size_t)warp * (size_t)U;

    // ---- binary search for prefix length (mask monotone 1..1 0..0) ----
    int lo = 0, hi = U;
    while (hi > lo) {
        const int step = (hi - lo + 31) >> 5;
        const int p = lo + lane * step;
        bool one = false;
        if (p < hi) one = (__ldg(unit_mask + base + p) > 0.5f);
        const unsigned ball = __ballot_sync(0xffffffffu, one);
        const int n1 = __popc(ball);
        if (n1 == 0) {
            hi = lo;
        } else {
            const int nl = lo + (n1 - 1) * step + 1;
            const int f0 = lo + n1 * step;
            hi = (f0 < hi) ? f0 : hi;
            lo = nl;
        }
    }
    const int visible = lo;

    // ---- first open index within the visible prefix (128-elem chunks) ----
    int fo = INT_MAX;
    for (int start = 0; start < visible; start += 128) {
        const int idx = start + lane * 4;
        int m = INT_MAX;
        if (idx < U) {
            if (idx + 3 < U) {
                const int4 v = __ldg((const int4*)(open_run + base + idx));
                if (v.x > 0 && idx + 0 < visible) m = min(m, idx + 0);
                if (v.y > 0 && idx + 1 < visible) m = min(m, idx + 1);
                if (v.z > 0 && idx + 2 < visible) m = min(m, idx + 2);
                if (v.w > 0 && idx + 3 < visible) m = min(m, idx + 3);
            } else {
                for (int e = 0; e < 4 && idx + e < U; e++)
                    if (idx + e < visible && __ldg(open_run + base + idx + e) > 0)
                        m = min(m, idx + e);
            }
        }
        const int wm = warpMin(m);
        const int bwm = __shfl_sync(0xffffffffu, wm, 0);
        if (bwm != INT_MAX) { fo = bwm; break; }
    }

    if (lane == 0) {
        g_visible[warp] = visible;
        g_first[warp]   = fo;
    }
}

// ---------------------------------------------------------------------------
// Main streaming kernel: U % 4 == 0, U <= BS*4. Never reads unit_mask or
// open_run. Low-register smem-staged structure (v3-style).
// ---------------------------------------------------------------------------
__global__ __launch_bounds__(BS, 4)
void rhythm_projector_v5(
    const float* __restrict__ anchor_src,
    const float* __restrict__ speech_budget,
    const float* __restrict__ pause_budget,
    const float* __restrict__ lr_unit,
    const float* __restrict__ pw_unit,
    const float* __restrict__ bl_unit,
    const float* __restrict__ phase_ptr,
    const float* __restrict__ backlog,
    const float* __restrict__ clock_delta,
    const int*   __restrict__ commit_frontier,
    float* __restrict__ out,
    int B, int U)
{
    const int row = blockIdx.x;
    const int tid = threadIdx.x;
    const size_t base = (size_t)row * (size_t)U;
    const size_t BU = (size_t)B * (size_t)U;

    __shared__ float4 s_sp[BS];
    __shared__ float4 s_sc[BS];
    __shared__ float s_f0[NW], s_f1[NW], s_f2[NW];
    __shared__ float s_bcast[2];

    const int visible    = g_visible[row];
    const int first_open = g_first[row];

    const int j = tid * 4;
    const bool in = (j < U);

    // -------- Pass A: load + elementwise -> smem + partial sums -------------
    float sum_sp = 0.f, sum_sc = 0.f;
    {
        float4 spv = make_float4(0.f, 0.f, 0.f, 0.f);
        float4 scv = spv;
        if (in) {
            const float4 ar = __ldcs((const float4*)(anchor_src + base + j));
            const float4 lr = __ldcs((const float4*)(lr_unit    + base + j));
            const float4 pw = __ldcs((const float4*)(pw_unit    + base + j));
            const float4 bl = __ldcs((const float4*)(bl_unit    + base + j));

            #define ELEM(c, e)                                                    \
            {                                                                     \
                if ((j + e) < visible) {                                          \
                    const float a  = fmaxf(ar.c, 1.0f);                           \
                    const float bb = a * __expf(lr.c);                            \
                    spv.c = fmaxf(fminf(bb, a * 3.0f), 1.0f);                     \
                    scv.c = fmaxf(pw.c, 0.f) * (0.5f + bl.c);                     \
                }                                                                 \
            }
            ELEM(x, 0) ELEM(y, 1) ELEM(z, 2) ELEM(w, 3)
            #undef ELEM
            sum_sp = (spv.x + spv.y) + (spv.z + spv.w);
            sum_sc = (scv.x + scv.y) + (scv.z + scv.w);
        }
        s_sp[tid] = spv;
        s_sc[tid] = scv;
    }

    // -------- block reduction (sum_sp, sum_sc) ------------------------------
    {
        float w0 = warpSum(sum_sp);
        float w1 = warpSum(sum_sc);
        const int wid = tid >> 5, lid = tid & 31;
        if (lid == 0) { s_f0[wid] = w0; s_f1[wid] = w1; }
        __syncthreads();
        if (wid == 0) {
            float v0 = (lid < NW) ? s_f0[lid] : 0.f;
            float v1 = (lid < NW) ? s_f1[lid] : 0.f;
            #pragma unroll
            for (int o = 8; o > 0; o >>= 1) {
                v0 += __shfl_down_sync(0xffffffffu, v0, o);
                v1 += __shfl_down_sync(0xffffffffu, v1, o);
            }
            if (lid == 0) { s_bcast[0] = v0; s_bcast[1] = v1; }
        }
        __syncthreads();
        sum_sp = s_bcast[0]; sum_sc = s_bcast[1];
    }

    // -------- scalar frontier logic (uniform across block) ------------------
    const float sbud = speech_budget[row];
    const float pbud = pause_budget[row];
    const float speech_scale = sbud / fmaxf(sum_sp, 1e-6f);

    const bool has_open = (first_open != INT_MAX);
    const int  closed   = has_open ? first_open : visible;
    const int  cap      = max(visible - 2, 0);   // TAIL_HOLD_UNITS
    int cand = min(cap, closed);
    const int prev = commit_frontier[row];
    const int bidx = min(max(cand - 1, 0), U - 1);
    const float bval = __ldg(bl_unit + base + bidx);   // uniform broadcast
    const bool soft = (cand > 0) && (cand < visible) && (bval < 0.45f);
    if (soft) cand = max(prev, cand - 1);
    const int commit = max(prev, cand);

    const bool  use_scores = (sum_sc > 0.f);
    const float wdenom = pbud / fmaxf(sum_sc, 1e-6f);
    const float fb     = pbud / fmaxf((float)visible, 1.f);

    // -------- Pass B: compute + streaming stores + window sums --------------
    float sum_eff = 0.f, exec_s = 0.f, src_s = 0.f;
    if (in) {
        const float4 spv = s_sp[tid];
        const float4 scv = s_sc[tid];
        float4 speech, pause, eff;

        // prefix mask: speech/pause already zero beyond visible;
        // effective = speech + pause exactly (m in {0,1}).
        #define ELEM(c, e)                                                     \
        {                                                                      \
            speech.c = spv.c * speech_scale;                                   \
            pause.c = use_scores ? (scv.c * wdenom)                            \
                                 : (((j + e) < visible) ? fb : 0.f);           \
            eff.c = speech.c + pause.c;                                        \
            sum_eff += eff.c;                                                  \
            const int je = j + e;                                              \
            if (je >= prev && je < commit) {                                   \
                exec_s += eff.c;                                               \
                src_s  += __ldg(anchor_src + base + je);                       \
            }                                                                  \
        }
        ELEM(x, 0) ELEM(y, 1) ELEM(z, 2) ELEM(w, 3)
        #undef ELEM

        __stcs((float4*)(out + base + j),          speech);
        __stcs((float4*)(out + BU + base + j),     pause);
        __stcs((float4*)(out + 2 * BU + base + j), eff);
    }

    // -------- final 3-way reduction + tail outputs --------------------------
    {
        float w0 = warpSum(sum_eff);
        float w1 = warpSum(exec_s);
        float w2 = warpSum(src_s);
        const int wid = tid >> 5, lid = tid & 31;
        __syncthreads();   // protect smem reuse
        if (lid == 0) { s_f0[wid] = w0; s_f1[wid] = w1; s_f2[wid] = w2; }
        __syncthreads();
        if (tid == 0) {
            float v0 = 0.f, v1 = 0.f, v2 = 0.f;
            #pragma unroll
            for (int i = 0; i < NW; i++) { v0 += s_f0[i]; v1 += s_f1[i]; v2 += s_f2[i]; }

            const bool adv = commit > prev;
            const float cd = clock_delta[row];
            const float next_clock = adv ? (cd + (v1 - v2)) : cd;
            const float next_backlog = adv ? fmaxf(next_clock, 0.f) : backlog[row];
            const float vt = fmaxf(v0, 1.f);
            float next_phase = phase_ptr[row];
            if (adv) next_phase = fminf(fmaxf(next_phase + v1 / vt, 0.f), 1.f);

            float* tail = out + 3 * BU;
            tail[row]         = (float)commit;
            tail[B + row]     = next_phase;
            tail[2 * B + row] = next_backlog;
            tail[3 * B + row] = next_clock;
        }
    }
}

// ---------------------------------------------------------------------------
// Scalar fallback kernel (any shape; self-contained, no prefix assumption)
// ---------------------------------------------------------------------------
template<int ITEMS>
__global__ __launch_bounds__(BS)
void rhythm_projector_scalar(
    const float* __restrict__ anchor_src,
    const float* __restrict__ unit_mask,
    const float* __restrict__ speech_budget,
    const float* __restrict__ pause_budget,
    const float* __restrict__ lr_unit,
    const float* __restrict__ pw_unit,
    const float* __restrict__ bl_unit,
    const float* __restrict__ phase_ptr,
    const float* __restrict__ backlog,
    const float* __restrict__ clock_delta,
    const int*   __restrict__ commit_frontier,
    const int*   __restrict__ open_run,
    float* __restrict__ out,
    int B, int U)
{
    const int row = blockIdx.x;
    const int tid = threadIdx.x;
    const size_t base = (size_t)row * (size_t)U;
    const size_t BU = (size_t)B * (size_t)U;

    __shared__ float s_f0[NW], s_f1[NW], s_f2[NW];
    __shared__ int   s_i0[NW];
    __shared__ float s_bcast[3];
    __shared__ int   s_ibcast;

    float sp[ITEMS], sc[ITEMS], msk[ITEMS];
    float sum_sp = 0.f, sum_sc = 0.f, sum_m = 0.f;
    int first_open = INT_MAX;

    #pragma unroll
    for (int k = 0; k < ITEMS; k++) {
        const int j = k * BS + tid;
        float m = 0.f, spv = 0.f, scv = 0.f;
        if (j < U) {
            const float arv = anchor_src[base + j];
            m               = unit_mask[base + j];
            const float lrv = lr_unit[base + j];
            const float pwv = pw_unit[base + j];
            const float blv = bl_unit[base + j];
            const int   opv = open_run[base + j];
            const float a   = fmaxf(arv, 1.0f);
            const float b   = a * __expf(lrv);
            spv = fmaxf(fminf(b, a * 3.0f), 1.0f) * m;
            scv = fmaxf(pwv, 0.f) * (0.5f + blv) * m;
            if (opv > 0 && m > 0.f) first_open = min(first_open, j);
        }
        sp[k] = spv; sc[k] = scv; msk[k] = m;
        sum_sp += spv; sum_sc += scv; sum_m += m;
    }

    {
        float w0 = warpSum(sum_sp), w1 = warpSum(sum_sc), w2 = warpSum(sum_m);
        int w3 = warpMin(first_open);
        const int wid = tid >> 5, lid = tid & 31;
        if (lid == 0) { s_f0[wid] = w0; s_f1[wid] = w1; s_f2[wid] = w2; s_i0[wid] = w3; }
        __syncthreads();
        if (wid == 0) {
            float v0 = (lid < NW) ? s_f0[lid] : 0.f;
            float v1 = (lid < NW) ? s_f1[lid] : 0.f;
            float v2 = (lid < NW) ? s_f2[lid] : 0.f;
            int   v3 = (lid < NW) ? s_i0[lid] : INT_MAX;
            #pragma unroll
            for (int o = 8; o > 0; o >>= 1) {
                v0 += __shfl_down_sync(0xffffffffu, v0, o);
                v1 += __shfl_down_sync(0xffffffffu, v1, o);
                v2 += __shfl_down_sync(0xffffffffu, v2, o);
                v3 = min(v3, __shfl_down_sync(0xffffffffu, v3, o));
            }
            if (lid == 0) { s_bcast[0] = v0; s_bcast[1] = v1; s_bcast[2] = v2; s_ibcast = v3; }
        }
        __syncthreads();
        sum_sp = s_bcast[0]; sum_sc = s_bcast[1]; sum_m = s_bcast[2];
        first_open = s_ibcast;
    }

    const float sbud = speech_budget[row];
    const float pbud = pause_budget[row];
    const float speech_scale = sbud / fmaxf(sum_sp, 1e-6f);
    const int  visible  = (int)sum_m;
    const bool has_open = (first_open != INT_MAX);
    const int  closed   = has_open ? first_open : visible;
    const int  cap      = max(visible - 2, 0);
    int cand = min(cap, closed);
    const int prev = commit_frontier[row];
    const int bidx = min(max(cand - 1, 0), U - 1);
    const float bval = __ldg(bl_unit + base + bidx);
    const bool soft = (cand > 0) && (cand < visible) && (bval < 0.45f);
    if (soft) cand = max(prev, cand - 1);
    const int commit = max(prev, cand);

    const bool  use_scores = (sum_sc > 0.f);
    const float wdenom = 1.f / fmaxf(sum_sc, 1e-6f);
    const float fb     = 1.f / fmaxf(sum_m, 1.f);

    float sum_eff = 0.f, exec_s = 0.f, src_s = 0.f;
    #pragma unroll
    for (int k = 0; k < ITEMS; k++) {
        const int j = k * BS + tid;
        if (j < U) {
            const float speech = sp[k] * speech_scale;
            const float w      = use_scores ? (sc[k] * wdenom) : (msk[k] * fb);
            const float pause  = w * pbud;
            const float eff    = (speech + pause) * msk[k];
            out[base + j]          = speech;
            out[BU + base + j]     = pause;
            out[2 * BU + base + j] = eff;
            sum_eff += eff;
            if (j >= prev && j < commit) {
                exec_s += eff;
                src_s  += __ldg(anchor_src + base + j);
            }
        }
    }

    {
        float w0 = warpSum(sum_eff), w1 = warpSum(exec_s), w2 = warpSum(src_s);
        const int wid = tid >> 5, lid = tid & 31;
        if (lid == 0) { s_f0[wid] = w0; s_f1[wid] = w1; s_f2[wid] = w2; }
        __syncthreads();
        if (tid == 0) {
            float v0 = 0.f, v1 = 0.f, v2 = 0.f;
            #pragma unroll
            for (int i = 0; i < NW; i++) { v0 += s_f0[i]; v1 += s_f1[i]; v2 += s_f2[i]; }
            const bool adv = commit > prev;
            const float cd = clock_delta[row];
            const float next_clock = adv ? (cd + (v1 - v2)) : cd;
            const float next_backlog = adv ? fmaxf(next_clock, 0.f) : backlog[row];
            const float vt = fmaxf(v0, 1.f);
            float next_phase = phase_ptr[row];
            if (adv) next_phase = fminf(fmaxf(next_phase + v1 / vt, 0.f), 1.f);
            float* tail = out + 3 * BU;
            tail[row]         = (float)commit;
            tail[B + row]     = next_phase;
            tail[2 * B + row] = next_backlog;
            tail[3 * B + row] = next_clock;
        }
    }
}

extern "C" void kernel_launch(void* const* d_in, const int* in_sizes, int n_in,
                              void* d_out, int out_size)
{
    const float* anchor_src  = (const float*)d_in[0];
    const float* unit_mask   = (const float*)d_in[1];
    const float* sbud        = (const float*)d_in[2];
    const float* pbud        = (const float*)d_in[3];
    const float* lr_unit     = (const float*)d_in[4];
    const float* pw_unit     = (const float*)d_in[5];
    const float* bl_unit     = (const float*)d_in[6];
    const float* phase_ptr   = (const float*)d_in[7];
    const float* backlog     = (const float*)d_in[8];
    const float* clock_delta = (const float*)d_in[9];
    const int*   frontier    = (const int*)d_in[10];
    const int*   open_run    = (const int*)d_in[11];
    float* out = (float*)d_out;

    const int B = in_sizes[2];            // speech_budget_win has B elements
    const int U = in_sizes[0] / B;        // dur_anchor_src has B*U

    if ((U & 3) == 0 && U <= BS * 4 && B <= MAX_ROWS) {
        const int preBlocks = (B + 7) / 8;       // 8 warps per 256-thread block
        precompute_row_stats<<<preBlocks, 256>>>(unit_mask, open_run, B, U);
        rhythm_projector_v5<<<B, BS>>>(anchor_src, sbud, pbud, lr_unit, pw_unit,
            bl_unit, phase_ptr, backlog, clock_delta, frontier, out, B, U);
    } else {
        const int items = (U + BS - 1) / BS;
        dim3 grid(B), block(BS);
        #define LAUNCH(N) rhythm_projector_scalar<N><<<grid, block>>>(anchor_src,    \
            unit_mask, sbud, pbud, lr_unit, pw_unit, bl_unit, phase_ptr, backlog,    \
            clock_delta, frontier, open_run, out, B, U)
        if      (items <= 4)  LAUNCH(4);
        else if (items <= 8)  LAUNCH(8);
        else if (items <= 16) LAUNCH(16);
        else                  LAUNCH(32);
        #undef LAUNCH
    }
}